// round 16
// baseline (speedup 1.0000x reference)
#include <cuda_runtime.h>
#include <cuda_bf16.h>
#include <cstdint>
#include <math.h>

#define BSZ 32
#define LL 4096
#define HH 512
#define PP 384
#define VV 32
#define TOUT 16
#define NC 16
#define CHUNK 255          // (LL - TOUT) / NC
#define RR (BSZ*TOUT)      // 512 output rows
#define KXC (2*PP)         // 768
#define MCE 896            // CE rows padded (800 used)
#define NZF 2              // K-splits for final gemm

typedef unsigned long long u64;
typedef __nv_bfloat16 bf16;

// ---------------- scratch (device globals) ----------------
__device__ __align__(16) float2 d_Lbar[PP];
__device__ __align__(16) float2 d_Wpow[NC*PP];
__device__ __align__(16) float  d_BgRe[VV*PP];
__device__ __align__(16) float  d_BgIm[VV*PP];
__device__ __align__(16) float  d_xpartRe[BSZ*NC*PP];
__device__ __align__(16) float  d_xpartIm[BSZ*NC*PP];
__device__ __align__(16) bf16   d_CEhi[MCE*HH];     // [Cre^T;Cim^T;embed*D;pad] hi
__device__ __align__(16) bf16   d_CElo[MCE*HH];
__device__ __align__(16) bf16   d_W1thi[HH*HH];     // W1^T [n][k]
__device__ __align__(16) bf16   d_W1tlo[HH*HH];
__device__ __align__(16) bf16   d_Gthi[HH*KXC];     // (Cbig@W1)^T [n][k=768]
__device__ __align__(16) bf16   d_Gtlo[HH*KXC];
__device__ __align__(16) bf16   d_Xhi[RR*KXC];
__device__ __align__(16) bf16   d_Xlo[RR*KXC];
__device__ __align__(16) float  d_E1[VV*HH];        // (embed*D)@W1 + b1
__device__ __align__(16) float  d_W2t[VV*HH];
__device__ __align__(16) float  d_part[NZF*RR*HH];  // 2 MB partials

// ---------------- packed f32x2 helpers (scan path) ----------------
__device__ __forceinline__ u64 pk2(float lo, float hi) {
    u64 r; asm("mov.b64 %0, {%1, %2};" : "=l"(r) : "f"(lo), "f"(hi)); return r;
}
__device__ __forceinline__ float2 upk(u64 x) {
    float lo, hi; asm("mov.b64 {%0, %1}, %2;" : "=f"(lo), "=f"(hi) : "l"(x));
    return make_float2(lo, hi);
}
__device__ __forceinline__ u64 fma2(u64 a, u64 b, u64 c) {
    u64 d; asm("fma.rn.f32x2 %0, %1, %2, %3;" : "=l"(d) : "l"(a), "l"(b), "l"(c));
    return d;
}

// ---------------- mma.sync helpers ----------------
__device__ __forceinline__ uint32_t smem_u32(const void* p) {
    uint32_t a;
    asm("{ .reg .u64 t; cvta.to.shared.u64 t, %1; cvt.u32.u64 %0, t; }"
        : "=r"(a) : "l"(p));
    return a;
}
__device__ __forceinline__ void ldsm4(uint32_t* r, uint32_t addr) {
    asm volatile("ldmatrix.sync.aligned.m8n8.x4.shared.b16 {%0,%1,%2,%3}, [%4];"
        : "=r"(r[0]), "=r"(r[1]), "=r"(r[2]), "=r"(r[3]) : "r"(addr));
}
__device__ __forceinline__ void mma16816(float* c, const uint32_t* a, const uint32_t* b) {
    asm volatile("mma.sync.aligned.m16n8k16.row.col.f32.bf16.bf16.f32 "
        "{%0,%1,%2,%3}, {%4,%5,%6,%7}, {%8,%9}, {%0,%1,%2,%3};"
        : "+f"(c[0]), "+f"(c[1]), "+f"(c[2]), "+f"(c[3])
        : "r"(a[0]), "r"(a[1]), "r"(a[2]), "r"(a[3]), "r"(b[0]), "r"(b[1]));
}

// ---------------- bf16 hi/lo split ----------------
__device__ __forceinline__ void bfsplit(float v, bf16& h, bf16& l) {
    h = __float2bfloat16(v);
    l = __float2bfloat16(v - __bfloat162float(h));
}

// ===== mma core: 64x64 tile, 4 warps, 3 hi/lo passes accumulated in-register =====
struct MmaSmem { bf16 sA[64][40]; bf16 sB[64][40]; };

__device__ __forceinline__ void mma_core3(
    const bf16* __restrict__ Ahi, const bf16* __restrict__ Alo,
    const bf16* __restrict__ Bhi, const bf16* __restrict__ Blo,
    int K, int k0, int Klen, int row0, int col0,
    float acc[2][4][4], MmaSmem* sm)
{
    int tid = threadIdx.x;
    int warp = tid >> 5, lane = tid & 31;
    int wm = warp >> 1, wn = warp & 1;
    uint32_t aBase = smem_u32(&sm->sA[0][0]);
    uint32_t bBase = smem_u32(&sm->sB[0][0]);
    int arow = wm*32 + (lane & 15);
    int acol = (lane >> 4) * 8;
    int brow = wn*32 + (lane & 7) + ((lane >> 4) << 3);
    int bcol = ((lane >> 3) & 1) * 8;

    #pragma unroll 1
    for (int pass = 0; pass < 3; ++pass) {
        const bf16* Ap = (pass == 1) ? Alo : Ahi;
        const bf16* Bp = (pass == 2) ? Blo : Bhi;
        #pragma unroll 1
        for (int kk = 0; kk < Klen; kk += 32) {
            #pragma unroll
            for (int q = 0; q < 2; ++q) {
                int item = q*128 + tid;          // 0..255
                int r = item >> 2, kg = item & 3;
                *(uint4*)&sm->sA[r][kg*8] =
                    *(const uint4*)(Ap + (size_t)(row0 + r)*K + k0 + kk + kg*8);
                *(uint4*)&sm->sB[r][kg*8] =
                    *(const uint4*)(Bp + (size_t)(col0 + r)*K + k0 + kk + kg*8);
            }
            __syncthreads();
            #pragma unroll
            for (int k16 = 0; k16 < 32; k16 += 16) {
                uint32_t a[2][4], b[2][4];
                ldsm4(a[0], aBase + (uint32_t)(((arow)*40      + k16 + acol) * 2));
                ldsm4(a[1], aBase + (uint32_t)(((arow + 16)*40 + k16 + acol) * 2));
                ldsm4(b[0], bBase + (uint32_t)(((brow)*40      + k16 + bcol) * 2));
                ldsm4(b[1], bBase + (uint32_t)(((brow + 16)*40 + k16 + bcol) * 2));
                #pragma unroll
                for (int am = 0; am < 2; ++am) {
                    mma16816(acc[am][0], a[am], &b[0][0]);
                    mma16816(acc[am][1], a[am], &b[0][2]);
                    mma16816(acc[am][2], a[am], &b[1][0]);
                    mma16816(acc[am][3], a[am], &b[1][2]);
                }
            }
            __syncthreads();
        }
    }
}

// ================= K1: all preprocessing (1068 blocks) =================
__global__ void __launch_bounds__(256) prep_all(
    const float* __restrict__ Lre, const float* __restrict__ Lim,
    const float* __restrict__ logstep,
    const float* __restrict__ embed, const float* __restrict__ Bre,
    const float* __restrict__ Bim, const float* __restrict__ W2,
    const float* __restrict__ Cre, const float* __restrict__ Cim,
    const float* __restrict__ D, const float* __restrict__ W1)
{
    int bid = blockIdx.x, tid = threadIdx.x;
    if (bid >= 812) {                            // W1t hi/lo tile transpose
        __shared__ float ts[32][33];
        int m = bid - 812;
        int ktile = m & 15, ntile = m >> 4;
        int k0 = ktile * 32, n0 = ntile * 32;
        int ii = tid & 31, jj0 = tid >> 5;
        #pragma unroll
        for (int q = 0; q < 4; ++q) {
            int jj = jj0 + 8*q;
            ts[jj][ii] = W1[(size_t)(k0 + jj)*HH + n0 + ii];
        }
        __syncthreads();
        #pragma unroll
        for (int q = 0; q < 4; ++q) {
            int i2 = jj0 + 8*q;
            float v = ts[tid & 31][i2];
            bf16 h, l; bfsplit(v, h, l);
            size_t o = (size_t)(n0 + i2)*HH + k0 + (tid & 31);
            d_W1thi[o] = h; d_W1tlo[o] = l;
        }
        return;
    }
    if (bid >= 800) {                            // zero-pad CE rows 800..895
        int idx0 = (bid - 800) * 1024 + tid;
        uint2 z = make_uint2(0u, 0u);
        #pragma unroll
        for (int q = 0; q < 4; ++q) {
            int idx = idx0 + q*256;
            ((uint2*)(d_CEhi + (size_t)800*HH))[idx] = z;
            ((uint2*)(d_CElo + (size_t)800*HH))[idx] = z;
        }
        return;
    }
    if (bid >= 784) {                            // embed*D rows 768..799
        int i = bid - 784;
        for (int e = i*1024 + tid; e < (i+1)*1024; e += 256) {
            int v = e >> 9, h = e & 511;
            float val = embed[v*HH + h] * D[h];
            bf16 bh, bl; bfsplit(val, bh, bl);
            size_t o = (size_t)(KXC + v)*HH + h;
            d_CEhi[o] = bh; d_CElo[o] = bl;
        }
        return;
    }
    if (bid >= 400) {                            // CE rows [0,768) tile transpose
        __shared__ float ts[32][33];
        int m = bid - 400;
        int ktile = m % 24, htile = m / 24;
        int k0 = ktile * 32, h0 = htile * 32;
        const float* src = (k0 < PP) ? Cre : Cim;
        int kk0 = (k0 < PP) ? k0 : k0 - PP;
        int j = tid & 31, i0 = tid >> 5;
        #pragma unroll
        for (int q = 0; q < 4; ++q) {
            int i = i0 + 8*q;
            ts[j][i] = src[(size_t)(h0 + i)*PP + kk0 + j];
        }
        __syncthreads();
        #pragma unroll
        for (int q = 0; q < 4; ++q) {
            int jk = i0 + 8*q;
            float v = ts[jk][j];
            bf16 h, l; bfsplit(v, h, l);
            size_t o = (size_t)(k0 + jk)*HH + h0 + j;
            d_CEhi[o] = h; d_CElo[o] = l;
        }
        return;
    }
    if (bid >= PP) {                             // transpose W2 (fp32)
        int i = bid - PP;
        for (int e = i*1024 + tid; e < (i+1)*1024; e += 256) {
            int h = e >> 5, v = e & 31;
            d_W2t[v*HH + h] = W2[e];
        }
        return;
    }
    int p = bid;
    __shared__ float sBr[HH], sBi[HH];
    __shared__ float2 sg;
    for (int h = tid; h < HH; h += 256) {
        sBr[h] = Bre[p*HH + h];
        sBi[h] = Bim[p*HH + h];
    }
    if (tid < NC) {
        float lre = Lre[p], lim = Lim[p];
        float step = (float)exp((double)logstep[p]);
        float zr = lre * step, zi = lim * step;
        double m = exp((double)zr);
        double sv, cv; sincos((double)zi, &sv, &cv);
        float br = (float)(m * cv), bi = (float)(m * sv);
        if (tid == 0) {
            d_Lbar[p] = make_float2(br, bi);
            float ar = br - 1.f, ai = bi;
            float den = lre*lre + lim*lim;
            sg = make_float2((ar*lre + ai*lim)/den, (ai*lre - ar*lim)/den);
        }
        double dbr = (double)br, dbi = (double)bi;
        double lr = log(sqrt(dbr*dbr + dbi*dbi));
        double th = atan2(dbi, dbr);
        double e  = (double)(CHUNK * tid);
        double mm = exp(lr * e);
        double s2, c2; sincos(th * e, &s2, &c2);
        d_Wpow[tid*PP + p] = make_float2((float)(mm*c2), (float)(mm*s2));
    }
    __syncthreads();
    int warp = tid >> 5, lane = tid & 31;
    float2 g = sg;
    for (int v = warp; v < VV; v += 8) {
        float sr = 0.f, si = 0.f;
        for (int h = lane; h < HH; h += 32) {
            float e = embed[v*HH + h];
            sr = fmaf(e, sBr[h], sr);
            si = fmaf(e, sBi[h], si);
        }
        #pragma unroll
        for (int o = 16; o; o >>= 1) {
            sr += __shfl_xor_sync(0xffffffffu, sr, o);
            si += __shfl_xor_sync(0xffffffffu, si, o);
        }
        if (lane == 0) {
            d_BgRe[v*PP + p] = g.x*sr - g.y*si;
            d_BgIm[v*PP + p] = g.x*si + g.y*sr;
        }
    }
}

// ===== K2: scan blocks [0,512) + Gt-gemm blocks [512,624) fused =====
// Gt = W1t @ CE^T : A=W1t[n][k], B=CE[m][k]; full K in-register; direct epilogue.
__global__ void __launch_bounds__(128) scan_gemmGt(const int* __restrict__ tokens,
                                                   const float* __restrict__ b1) {
    __shared__ __align__(16) char smbuf[sizeof(MmaSmem)];
    int bid = blockIdx.x;
    if (bid < NC*BSZ) {
        int* stok = (int*)smbuf;
        int b = bid / NC, c = bid % NC, t = threadIdx.x;
        for (int i = t; i < CHUNK; i += 128) stok[i] = tokens[b*LL + c*CHUNK + i];
        __syncthreads();
        if (t < 96) {
            int p0 = t * 4;
            float2 L0 = d_Lbar[p0+0], L1 = d_Lbar[p0+1];
            float2 L2 = d_Lbar[p0+2], L3 = d_Lbar[p0+3];
            u64 LrA = pk2(L0.x, L1.x), LrB = pk2(L2.x, L3.x);
            u64 LiA = pk2(L0.y, L1.y), LiB = pk2(L2.y, L3.y);
            u64 nLiA = pk2(-L0.y, -L1.y), nLiB = pk2(-L2.y, -L3.y);
            u64 XR0 = 0ull, XR1 = 0ull, XI0 = 0ull, XI1 = 0ull;
            const float* bgr = d_BgRe + p0;
            const float* bgi = d_BgIm + p0;
            #pragma unroll 5
            for (int i = 0; i < CHUNK; ++i) {
                int off = stok[i] * PP;
                ulonglong2 br = *(const ulonglong2*)(bgr + off);
                ulonglong2 bi = *(const ulonglong2*)(bgi + off);
                u64 nR0 = fma2(LrA, XR0, fma2(nLiA, XI0, br.x));
                u64 nI0 = fma2(LrA, XI0, fma2(LiA,  XR0, bi.x));
                u64 nR1 = fma2(LrB, XR1, fma2(nLiB, XI1, br.y));
                u64 nI1 = fma2(LrB, XI1, fma2(LiB,  XR1, bi.y));
                XR0 = nR0; XI0 = nI0; XR1 = nR1; XI1 = nI1;
            }
            int base = (b*NC + c)*PP + p0;
            *(ulonglong2*)(d_xpartRe + base) = make_ulonglong2(XR0, XR1);
            *(ulonglong2*)(d_xpartIm + base) = make_ulonglong2(XI0, XI1);
        }
    } else {
        int g = bid - NC*BSZ;                    // 0..111
        int by = g / 14, bx = g % 14;            // by: n-tiles(8), bx: m-tiles(14)
        int row0 = by * 64, col0 = bx * 64;
        float acc[2][4][4];
        #pragma unroll
        for (int i = 0; i < 2; ++i)
            #pragma unroll
            for (int j = 0; j < 4; ++j)
                #pragma unroll
                for (int q = 0; q < 4; ++q) acc[i][j][q] = 0.f;
        mma_core3(d_W1thi, d_W1tlo, d_CEhi, d_CElo, HH, 0, HH,
                  row0, col0, acc, (MmaSmem*)smbuf);
        // epilogue: out[n][m] ; m<768 -> Gt hi/lo ; 768<=m<800 -> E1
        int tid = threadIdx.x;
        int warp = tid >> 5, lane = tid & 31;
        int wm = warp >> 1, wn = warp & 1;
        int nBase = row0 + wm*32 + (lane >> 2);
        int mBase = col0 + wn*32 + (lane & 3)*2;
        #pragma unroll
        for (int am = 0; am < 2; ++am) {
            #pragma unroll
            for (int half = 0; half < 2; ++half) {   // c0c1 vs c2c3
                int n = nBase + am*16 + half*8;
                #pragma unroll
                for (int nb = 0; nb < 4; ++nb) {
                    int m = mBase + nb*8;
                    float v0 = acc[am][nb][half*2 + 0];
                    float v1 = acc[am][nb][half*2 + 1];
                    if (m < KXC) {
                        bf16 h0, l0, h1, l1;
                        bfsplit(v0, h0, l0); bfsplit(v1, h1, l1);
                        size_t o = (size_t)n*KXC + m;
                        *(__nv_bfloat162*)(d_Gthi + o) = __nv_bfloat162(h0, h1);
                        *(__nv_bfloat162*)(d_Gtlo + o) = __nv_bfloat162(l0, l1);
                    } else if (m < KXC + VV) {
                        float bv = b1[n];
                        d_E1[(size_t)(m - KXC)*HH + n]     = v0 + bv;
                        d_E1[(size_t)(m - KXC + 1)*HH + n] = v1 + bv;
                    }
                }
            }
        }
    }
}

// ================= K3: combine + emission (prefetched) -> Xhi/Xlo ==============
__global__ void __launch_bounds__(192) combine_emit(const int* __restrict__ tokens) {
    int b = blockIdx.x;
    int p = blockIdx.y * 192 + threadIdx.x;
    float2 Lb = d_Lbar[p];
    float xr = 0.f, xi = 0.f;
    #pragma unroll
    for (int c = 0; c < NC; ++c) {
        float2 W = d_Wpow[(NC - 1 - c)*PP + p];
        int base = (b*NC + c)*PP + p;
        float pr = d_xpartRe[base], pi = d_xpartIm[base];
        xr = fmaf(W.x, pr, fmaf(-W.y, pi, xr));
        xi = fmaf(W.x, pi, fmaf( W.y, pr, xi));
    }
    float pbr[TOUT], pbi[TOUT];
    #pragma unroll
    for (int j = 0; j < TOUT; ++j) {
        int tok = tokens[b*LL + (LL - TOUT) + j];
        pbr[j] = d_BgRe[tok*PP + p];
        pbi[j] = d_BgIm[tok*PP + p];
    }
    #pragma unroll
    for (int j = 0; j < TOUT; ++j) {
        float nr = fmaf(Lb.x, xr, fmaf(-Lb.y, xi, pbr[j]));
        float ni = fmaf(Lb.y, xr, fmaf( Lb.x, xi, pbi[j]));
        xr = nr; xi = ni;
        int r = b*TOUT + j;
        bf16 h, l;
        bfsplit(2.f * xr, h, l);
        d_Xhi[r*KXC + p] = h; d_Xlo[r*KXC + p] = l;
        bfsplit(-2.f * xi, h, l);
        d_Xhi[r*KXC + PP + p] = h; d_Xlo[r*KXC + PP + p] = l;
    }
}

// ===== K4: y partials = X @ G (A=X[m][k], B=Gt[n][k]); 3 passes in-reg, K-split 2 =====
__global__ void __launch_bounds__(128) gemmF() {
    __shared__ __align__(16) MmaSmem sm;
    int bx = blockIdx.x, by = blockIdx.y, z = blockIdx.z;
    int row0 = by * 64, col0 = bx * 64;
    int Khalf = KXC / NZF;
    float acc[2][4][4];
    #pragma unroll
    for (int i = 0; i < 2; ++i)
        #pragma unroll
        for (int j = 0; j < 4; ++j)
            #pragma unroll
            for (int q = 0; q < 4; ++q) acc[i][j][q] = 0.f;
    mma_core3(d_Xhi, d_Xlo, d_Gthi, d_Gtlo, KXC, z*Khalf, Khalf,
              row0, col0, acc, &sm);
    float* outp = d_part + (size_t)z * (RR*HH);
    int tid = threadIdx.x;
    int warp = tid >> 5, lane = tid & 31;
    int wm = warp >> 1, wn = warp & 1;
    int mEp = row0 + wm*32 + (lane >> 2);
    int nEp = col0 + wn*32 + (lane & 3)*2;
    #pragma unroll
    for (int am = 0; am < 2; ++am) {
        #pragma unroll
        for (int nb = 0; nb < 4; ++nb) {
            int m = mEp + am*16;
            int n = nEp + nb*8;
            *(float2*)(outp + (size_t)m*HH + n)       = make_float2(acc[am][nb][0], acc[am][nb][1]);
            *(float2*)(outp + (size_t)(m + 8)*HH + n) = make_float2(acc[am][nb][2], acc[am][nb][3]);
        }
    }
}

// ===== mlp_tail: h1 = relu(sum 2 partials + E1[tok]), out = h1@W2t + b2 =====
__global__ void __launch_bounds__(256) mlp_tail(const int* __restrict__ tokens,
                                                const float* __restrict__ b2,
                                                float* __restrict__ out) {
    __shared__ __align__(16) float hs[4][HH];
    int tid = threadIdx.x;
    int r0 = blockIdx.x * 4;
    int e = tid * 8, row = e >> 9, col = e & 511;
    int rr = r0 + row;
    int tok = tokens[(rr >> 4)*LL + (LL - TOUT) + (rr & 15)];
    int gi = rr*HH + col;
    const float* e1 = d_E1 + (size_t)tok*HH + col;
    float4 s0 = *(const float4*)(e1);
    float4 s1 = *(const float4*)(e1 + 4);
    #pragma unroll
    for (int z = 0; z < NZF; ++z) {
        const float* pp = d_part + (size_t)z*RR*HH + gi;
        float4 p0 = *(const float4*)pp;
        float4 p1 = *(const float4*)(pp + 4);
        s0.x += p0.x; s0.y += p0.y; s0.z += p0.z; s0.w += p0.w;
        s1.x += p1.x; s1.y += p1.y; s1.z += p1.z; s1.w += p1.w;
    }
    s0.x = fmaxf(s0.x, 0.f); s0.y = fmaxf(s0.y, 0.f);
    s0.z = fmaxf(s0.z, 0.f); s0.w = fmaxf(s0.w, 0.f);
    s1.x = fmaxf(s1.x, 0.f); s1.y = fmaxf(s1.y, 0.f);
    s1.z = fmaxf(s1.z, 0.f); s1.w = fmaxf(s1.w, 0.f);
    *(float4*)&hs[row][col]     = s0;
    *(float4*)&hs[row][col + 4] = s1;
    __syncthreads();
    if (tid < 128) {
        int rw = tid >> 5, v = tid & 31;
        const float* wr = d_W2t + (size_t)v*HH;
        u64 a = 0ull, b = 0ull;
        #pragma unroll 8
        for (int h = 0; h < HH; h += 4) {
            ulonglong2 hv = *(const ulonglong2*)&hs[rw][h];
            ulonglong2 wv = *(const ulonglong2*)(wr + h);
            a = fma2(hv.x, wv.x, a);
            b = fma2(hv.y, wv.y, b);
        }
        float2 fa = upk(a), fb = upk(b);
        out[(r0 + rw)*VV + v] = fa.x + fa.y + fb.x + fb.y + b2[v];
    }
}

// ================= launcher =================
extern "C" void kernel_launch(void* const* d_in, const int* in_sizes, int n_in,
                              void* d_out, int out_size) {
    const int*   tokens  = (const int*)  d_in[0];
    const float* embed   = (const float*)d_in[1];
    const float* Lre     = (const float*)d_in[2];
    const float* Lim     = (const float*)d_in[3];
    const float* Bre     = (const float*)d_in[4];
    const float* Bim     = (const float*)d_in[5];
    const float* Cre     = (const float*)d_in[6];
    const float* Cim     = (const float*)d_in[7];
    const float* D       = (const float*)d_in[8];
    const float* logstep = (const float*)d_in[9];
    const float* W1      = (const float*)d_in[10];
    const float* b1      = (const float*)d_in[11];
    const float* W2      = (const float*)d_in[12];
    const float* b2      = (const float*)d_in[13];
    float* out = (float*)d_out;

    prep_all<<<1068, 256>>>(Lre, Lim, logstep, embed, Bre, Bim, W2, Cre, Cim, D, W1);
    scan_gemmGt<<<NC*BSZ + 112, 128>>>(tokens, b1);
    combine_emit<<<dim3(BSZ, 2), 192>>>(tokens);
    gemmF<<<dim3(8, 8, NZF), 128>>>();
    mlp_tail<<<RR/4, 256>>>(tokens, b2, out);
}

// round 17
// speedup vs baseline: 1.2421x; 1.2421x over previous
#include <cuda_runtime.h>
#include <cuda_bf16.h>
#include <cstdint>
#include <math.h>

#define BSZ 32
#define LL 4096
#define HH 512
#define PP 384
#define VV 32
#define TOUT 16
#define NC 16
#define CHUNK 255          // (LL - TOUT) / NC
#define RR (BSZ*TOUT)      // 512 output rows
#define KXC (2*PP)         // 768
#define MCE 896            // CE rows padded (800 used)
#define NZG 3              // pass-splits for Gt gemm (full K each)
#define NZF 6              // 3 passes x 2 K-splits for final gemm

typedef unsigned long long u64;
typedef __nv_bfloat16 bf16;

// ---------------- scratch (device globals) ----------------
__device__ __align__(16) float2 d_Lbar[PP];
__device__ __align__(16) float2 d_Wpow[NC*PP];
__device__ __align__(16) float  d_BgRe[VV*PP];
__device__ __align__(16) float  d_BgIm[VV*PP];
__device__ __align__(16) float  d_xpartRe[BSZ*NC*PP];
__device__ __align__(16) float  d_xpartIm[BSZ*NC*PP];
__device__ __align__(16) bf16   d_CEhi[MCE*HH];     // [Cre^T;Cim^T;embed*D;pad] hi
__device__ __align__(16) bf16   d_CElo[MCE*HH];
__device__ __align__(16) bf16   d_W1thi[HH*HH];     // W1^T [n][k]
__device__ __align__(16) bf16   d_W1tlo[HH*HH];
__device__ __align__(16) bf16   d_Gthi[HH*KXC];     // (Cbig@W1)^T [n][k=768]
__device__ __align__(16) bf16   d_Gtlo[HH*KXC];
__device__ __align__(16) bf16   d_Xhi[RR*KXC];
__device__ __align__(16) bf16   d_Xlo[RR*KXC];
__device__ __align__(16) float  d_E1[VV*HH];        // (embed*D)@W1 + b1
__device__ __align__(16) float  d_W2t[VV*HH];
__device__ __align__(16) float  d_part[NZF*RR*HH];  // 6.3 MB partials (shared Gt/F)

// ---------------- packed f32x2 helpers (scan path) ----------------
__device__ __forceinline__ u64 pk2(float lo, float hi) {
    u64 r; asm("mov.b64 %0, {%1, %2};" : "=l"(r) : "f"(lo), "f"(hi)); return r;
}
__device__ __forceinline__ float2 upk(u64 x) {
    float lo, hi; asm("mov.b64 {%0, %1}, %2;" : "=f"(lo), "=f"(hi) : "l"(x));
    return make_float2(lo, hi);
}
__device__ __forceinline__ u64 fma2(u64 a, u64 b, u64 c) {
    u64 d; asm("fma.rn.f32x2 %0, %1, %2, %3;" : "=l"(d) : "l"(a), "l"(b), "l"(c));
    return d;
}

// ---------------- mma.sync helpers ----------------
__device__ __forceinline__ uint32_t smem_u32(const void* p) {
    uint32_t a;
    asm("{ .reg .u64 t; cvta.to.shared.u64 t, %1; cvt.u32.u64 %0, t; }"
        : "=r"(a) : "l"(p));
    return a;
}
__device__ __forceinline__ void ldsm4(uint32_t* r, uint32_t addr) {
    asm volatile("ldmatrix.sync.aligned.m8n8.x4.shared.b16 {%0,%1,%2,%3}, [%4];"
        : "=r"(r[0]), "=r"(r[1]), "=r"(r[2]), "=r"(r[3]) : "r"(addr));
}
__device__ __forceinline__ void mma16816(float* c, const uint32_t* a, const uint32_t* b) {
    asm volatile("mma.sync.aligned.m16n8k16.row.col.f32.bf16.bf16.f32 "
        "{%0,%1,%2,%3}, {%4,%5,%6,%7}, {%8,%9}, {%0,%1,%2,%3};"
        : "+f"(c[0]), "+f"(c[1]), "+f"(c[2]), "+f"(c[3])
        : "r"(a[0]), "r"(a[1]), "r"(a[2]), "r"(a[3]), "r"(b[0]), "r"(b[1]));
}

// ---------------- bf16 hi/lo split ----------------
__device__ __forceinline__ void bfsplit(float v, bf16& h, bf16& l) {
    h = __float2bfloat16(v);
    l = __float2bfloat16(v - __bfloat162float(h));
}

// ===== shared mma GEMM body: 64x64 tile, 4 warps, single pass, K range =====
struct MmaSmem { bf16 sA[64][40]; bf16 sB[64][40]; };

__device__ __forceinline__ void gemm_mma_body(
    const bf16* __restrict__ Ap, const bf16* __restrict__ Bp,
    int K, int k0, int Klen, int Nstride,
    int bx, int by, float* outp, MmaSmem* sm)
{
    int tid = threadIdx.x & 127;
    int warp = tid >> 5, lane = tid & 31;
    int wm = warp >> 1, wn = warp & 1;
    int row0 = by * 64, col0 = bx * 64;

    float acc[2][4][4];
    #pragma unroll
    for (int i = 0; i < 2; ++i)
        #pragma unroll
        for (int j = 0; j < 4; ++j)
            #pragma unroll
            for (int q = 0; q < 4; ++q) acc[i][j][q] = 0.f;

    uint32_t aBase = smem_u32(&sm->sA[0][0]);
    uint32_t bBase = smem_u32(&sm->sB[0][0]);
    int arow = wm*32 + (lane & 15);
    int acol = (lane >> 4) * 8;
    int brow = wn*32 + (lane & 7) + ((lane >> 4) << 3);
    int bcol = ((lane >> 3) & 1) * 8;

    for (int kk = 0; kk < Klen; kk += 32) {
        #pragma unroll
        for (int q = 0; q < 2; ++q) {
            int item = q*128 + tid;              // 0..255
            int r = item >> 2, kg = item & 3;
            *(uint4*)&sm->sA[r][kg*8] =
                *(const uint4*)(Ap + (size_t)(row0 + r)*K + k0 + kk + kg*8);
            *(uint4*)&sm->sB[r][kg*8] =
                *(const uint4*)(Bp + (size_t)(col0 + r)*K + k0 + kk + kg*8);
        }
        __syncthreads();
        #pragma unroll
        for (int k16 = 0; k16 < 32; k16 += 16) {
            uint32_t a[2][4], b[2][4];
            ldsm4(a[0], aBase + (uint32_t)(((arow)*40      + k16 + acol) * 2));
            ldsm4(a[1], aBase + (uint32_t)(((arow + 16)*40 + k16 + acol) * 2));
            ldsm4(b[0], bBase + (uint32_t)(((brow)*40      + k16 + bcol) * 2));
            ldsm4(b[1], bBase + (uint32_t)(((brow + 16)*40 + k16 + bcol) * 2));
            #pragma unroll
            for (int am = 0; am < 2; ++am) {
                mma16816(acc[am][0], a[am], &b[0][0]);
                mma16816(acc[am][1], a[am], &b[0][2]);
                mma16816(acc[am][2], a[am], &b[1][0]);
                mma16816(acc[am][3], a[am], &b[1][2]);
            }
        }
        __syncthreads();
    }
    int mEp = row0 + wm*32 + (lane >> 2);
    int nEp = col0 + wn*32 + (lane & 3)*2;
    #pragma unroll
    for (int am = 0; am < 2; ++am) {
        #pragma unroll
        for (int nb = 0; nb < 4; ++nb) {
            int m = mEp + am*16;
            int n = nEp + nb*8;
            *(float2*)(outp + (size_t)m*Nstride + n)       = make_float2(acc[am][nb][0], acc[am][nb][1]);
            *(float2*)(outp + (size_t)(m + 8)*Nstride + n) = make_float2(acc[am][nb][2], acc[am][nb][3]);
        }
    }
}

// ================= K1: all preprocessing (1068 blocks) =================
__global__ void __launch_bounds__(256) prep_all(
    const float* __restrict__ Lre, const float* __restrict__ Lim,
    const float* __restrict__ logstep,
    const float* __restrict__ embed, const float* __restrict__ Bre,
    const float* __restrict__ Bim, const float* __restrict__ W2,
    const float* __restrict__ Cre, const float* __restrict__ Cim,
    const float* __restrict__ D, const float* __restrict__ W1)
{
    int bid = blockIdx.x, tid = threadIdx.x;
    if (bid >= 812) {                            // W1t hi/lo tile transpose
        __shared__ float ts[32][33];
        int m = bid - 812;
        int ktile = m & 15, ntile = m >> 4;
        int k0 = ktile * 32, n0 = ntile * 32;
        int ii = tid & 31, jj0 = tid >> 5;
        #pragma unroll
        for (int q = 0; q < 4; ++q) {
            int jj = jj0 + 8*q;
            ts[jj][ii] = W1[(size_t)(k0 + jj)*HH + n0 + ii];
        }
        __syncthreads();
        #pragma unroll
        for (int q = 0; q < 4; ++q) {
            int i2 = jj0 + 8*q;
            float v = ts[tid & 31][i2];
            bf16 h, l; bfsplit(v, h, l);
            size_t o = (size_t)(n0 + i2)*HH + k0 + (tid & 31);
            d_W1thi[o] = h; d_W1tlo[o] = l;
        }
        return;
    }
    if (bid >= 800) {                            // zero-pad CE rows 800..895
        int idx0 = (bid - 800) * 1024 + tid;
        uint2 z = make_uint2(0u, 0u);
        #pragma unroll
        for (int q = 0; q < 4; ++q) {
            int idx = idx0 + q*256;
            ((uint2*)(d_CEhi + (size_t)800*HH))[idx] = z;
            ((uint2*)(d_CElo + (size_t)800*HH))[idx] = z;
        }
        return;
    }
    if (bid >= 784) {                            // embed*D rows 768..799
        int i = bid - 784;
        for (int e = i*1024 + tid; e < (i+1)*1024; e += 256) {
            int v = e >> 9, h = e & 511;
            float val = embed[v*HH + h] * D[h];
            bf16 bh, bl; bfsplit(val, bh, bl);
            size_t o = (size_t)(KXC + v)*HH + h;
            d_CEhi[o] = bh; d_CElo[o] = bl;
        }
        return;
    }
    if (bid >= 400) {                            // CE rows [0,768) tile transpose
        __shared__ float ts[32][33];
        int m = bid - 400;
        int ktile = m % 24, htile = m / 24;
        int k0 = ktile * 32, h0 = htile * 32;
        const float* src = (k0 < PP) ? Cre : Cim;
        int kk0 = (k0 < PP) ? k0 : k0 - PP;
        int j = tid & 31, i0 = tid >> 5;
        #pragma unroll
        for (int q = 0; q < 4; ++q) {
            int i = i0 + 8*q;
            ts[j][i] = src[(size_t)(h0 + i)*PP + kk0 + j];
        }
        __syncthreads();
        #pragma unroll
        for (int q = 0; q < 4; ++q) {
            int jk = i0 + 8*q;
            float v = ts[jk][j];
            bf16 h, l; bfsplit(v, h, l);
            size_t o = (size_t)(k0 + jk)*HH + h0 + j;
            d_CEhi[o] = h; d_CElo[o] = l;
        }
        return;
    }
    if (bid >= PP) {                             // transpose W2 (fp32)
        int i = bid - PP;
        for (int e = i*1024 + tid; e < (i+1)*1024; e += 256) {
            int h = e >> 5, v = e & 31;
            d_W2t[v*HH + h] = W2[e];
        }
        return;
    }
    int p = bid;
    __shared__ float sBr[HH], sBi[HH];
    __shared__ float2 sg;
    for (int h = tid; h < HH; h += 256) {
        sBr[h] = Bre[p*HH + h];
        sBi[h] = Bim[p*HH + h];
    }
    if (tid < NC) {
        float lre = Lre[p], lim = Lim[p];
        float step = (float)exp((double)logstep[p]);
        float zr = lre * step, zi = lim * step;
        double m = exp((double)zr);
        double sv, cv; sincos((double)zi, &sv, &cv);
        float br = (float)(m * cv), bi = (float)(m * sv);
        if (tid == 0) {
            d_Lbar[p] = make_float2(br, bi);
            float ar = br - 1.f, ai = bi;
            float den = lre*lre + lim*lim;
            sg = make_float2((ar*lre + ai*lim)/den, (ai*lre - ar*lim)/den);
        }
        double dbr = (double)br, dbi = (double)bi;
        double lr = log(sqrt(dbr*dbr + dbi*dbi));
        double th = atan2(dbi, dbr);
        double e  = (double)(CHUNK * tid);
        double mm = exp(lr * e);
        double s2, c2; sincos(th * e, &s2, &c2);
        d_Wpow[tid*PP + p] = make_float2((float)(mm*c2), (float)(mm*s2));
    }
    __syncthreads();
    int warp = tid >> 5, lane = tid & 31;
    float2 g = sg;
    for (int v = warp; v < VV; v += 8) {
        float sr = 0.f, si = 0.f;
        for (int h = lane; h < HH; h += 32) {
            float e = embed[v*HH + h];
            sr = fmaf(e, sBr[h], sr);
            si = fmaf(e, sBi[h], si);
        }
        #pragma unroll
        for (int o = 16; o; o >>= 1) {
            sr += __shfl_xor_sync(0xffffffffu, sr, o);
            si += __shfl_xor_sync(0xffffffffu, si, o);
        }
        if (lane == 0) {
            d_BgRe[v*PP + p] = g.x*sr - g.y*si;
            d_BgIm[v*PP + p] = g.x*si + g.y*sr;
        }
    }
}

// ===== K2: scan blocks [0,512) + Gt-gemm blocks [512,848) fused =====
// Gt partials: A=W1t[n][k], B=CE[m][k]; z=pass in [0,3), full K=512.
__global__ void __launch_bounds__(128) scan_gemmGt(const int* __restrict__ tokens) {
    __shared__ __align__(16) char smbuf[sizeof(MmaSmem)];
    int bid = blockIdx.x;
    if (bid < NC*BSZ) {
        int* stok = (int*)smbuf;
        int b = bid / NC, c = bid % NC, t = threadIdx.x;
        for (int i = t; i < CHUNK; i += 128) stok[i] = tokens[b*LL + c*CHUNK + i];
        __syncthreads();
        if (t < 96) {
            int p0 = t * 4;
            float2 L0 = d_Lbar[p0+0], L1 = d_Lbar[p0+1];
            float2 L2 = d_Lbar[p0+2], L3 = d_Lbar[p0+3];
            u64 LrA = pk2(L0.x, L1.x), LrB = pk2(L2.x, L3.x);
            u64 LiA = pk2(L0.y, L1.y), LiB = pk2(L2.y, L3.y);
            u64 nLiA = pk2(-L0.y, -L1.y), nLiB = pk2(-L2.y, -L3.y);
            u64 XR0 = 0ull, XR1 = 0ull, XI0 = 0ull, XI1 = 0ull;
            const float* bgr = d_BgRe + p0;
            const float* bgi = d_BgIm + p0;
            #pragma unroll 5
            for (int i = 0; i < CHUNK; ++i) {
                int off = stok[i] * PP;
                ulonglong2 br = *(const ulonglong2*)(bgr + off);
                ulonglong2 bi = *(const ulonglong2*)(bgi + off);
                u64 nR0 = fma2(LrA, XR0, fma2(nLiA, XI0, br.x));
                u64 nI0 = fma2(LrA, XI0, fma2(LiA,  XR0, bi.x));
                u64 nR1 = fma2(LrB, XR1, fma2(nLiB, XI1, br.y));
                u64 nI1 = fma2(LrB, XI1, fma2(LiB,  XR1, bi.y));
                XR0 = nR0; XI0 = nI0; XR1 = nR1; XI1 = nI1;
            }
            int base = (b*NC + c)*PP + p0;
            *(ulonglong2*)(d_xpartRe + base) = make_ulonglong2(XR0, XR1);
            *(ulonglong2*)(d_xpartIm + base) = make_ulonglong2(XI0, XI1);
        }
    } else {
        int g = bid - NC*BSZ;                    // 0..335
        int bz = g / 112;                        // pass
        int rem = g % 112;
        int by = rem / 14, bx = rem % 14;        // by: n-tiles(8), bx: m-tiles(14)
        const bf16* Ap = (bz == 1) ? d_W1tlo : d_W1thi;
        const bf16* Bp = (bz == 2) ? d_CElo  : d_CEhi;
        float* outp = d_part + (size_t)bz * ((size_t)HH * MCE);
        gemm_mma_body(Ap, Bp, HH, 0, HH, MCE, bx, by, outp, (MmaSmem*)smbuf);
    }
}

// ===== K3: combine_emit blocks [0,64) + reduceG blocks [64,512) fused =====
__global__ void __launch_bounds__(256) combine_reduceG(const int* __restrict__ tokens,
                                                       const float* __restrict__ b1) {
    int bid = blockIdx.x;
    if (bid < 64) {
        if (threadIdx.x >= 192) return;
        int b = bid >> 1;
        int p = (bid & 1) * 192 + threadIdx.x;
        float2 Lb = d_Lbar[p];
        float xr = 0.f, xi = 0.f;
        #pragma unroll
        for (int c = 0; c < NC; ++c) {
            float2 W = d_Wpow[(NC - 1 - c)*PP + p];
            int base = (b*NC + c)*PP + p;
            float pr = d_xpartRe[base], pi = d_xpartIm[base];
            xr = fmaf(W.x, pr, fmaf(-W.y, pi, xr));
            xi = fmaf(W.x, pi, fmaf( W.y, pr, xi));
        }
        float pbr[TOUT], pbi[TOUT];
        #pragma unroll
        for (int j = 0; j < TOUT; ++j) {
            int tok = tokens[b*LL + (LL - TOUT) + j];
            pbr[j] = d_BgRe[tok*PP + p];
            pbi[j] = d_BgIm[tok*PP + p];
        }
        #pragma unroll
        for (int j = 0; j < TOUT; ++j) {
            float nr = fmaf(Lb.x, xr, fmaf(-Lb.y, xi, pbr[j]));
            float ni = fmaf(Lb.y, xr, fmaf( Lb.x, xi, pbi[j]));
            xr = nr; xi = ni;
            int r = b*TOUT + j;
            bf16 h, l;
            bfsplit(2.f * xr, h, l);
            d_Xhi[r*KXC + p] = h; d_Xlo[r*KXC + p] = l;
            bfsplit(-2.f * xi, h, l);
            d_Xhi[r*KXC + PP + p] = h; d_Xlo[r*KXC + PP + p] = l;
        }
    } else {
        int idx = (bid - 64)*256 + threadIdx.x;  // 114688 float4 items
        int i4 = idx * 4;
        int n = i4 / MCE, m = i4 % MCE;
        if (m >= KXC + VV) return;
        float4 s = make_float4(0.f, 0.f, 0.f, 0.f);
        #pragma unroll
        for (int z = 0; z < NZG; ++z) {
            float4 p = *(const float4*)(d_part + (size_t)z*HH*MCE + i4);
            s.x += p.x; s.y += p.y; s.z += p.z; s.w += p.w;
        }
        if (m < KXC) {
            bf16 h0, l0, h1, l1, h2, l2, h3, l3;
            bfsplit(s.x, h0, l0); bfsplit(s.y, h1, l1);
            bfsplit(s.z, h2, l2); bfsplit(s.w, h3, l3);
            size_t o = (size_t)n*KXC + m;
            d_Gthi[o+0] = h0; d_Gthi[o+1] = h1; d_Gthi[o+2] = h2; d_Gthi[o+3] = h3;
            d_Gtlo[o+0] = l0; d_Gtlo[o+1] = l1; d_Gtlo[o+2] = l2; d_Gtlo[o+3] = l3;
        } else {
            float bv = b1[n];
            d_E1[(size_t)(m - KXC + 0)*HH + n] = s.x + bv;
            d_E1[(size_t)(m - KXC + 1)*HH + n] = s.y + bv;
            d_E1[(size_t)(m - KXC + 2)*HH + n] = s.z + bv;
            d_E1[(size_t)(m - KXC + 3)*HH + n] = s.w + bv;
        }
    }
}

// ===== K4: y partials = X @ G ; z in [0,6): pass = z>>1, K-half = z&1 =====
__global__ void __launch_bounds__(128) gemmF() {
    __shared__ __align__(16) MmaSmem sm;
    int z = blockIdx.z;
    int pass = z >> 1, ks = z & 1;
    const bf16* Ap = (pass == 1) ? d_Xlo  : d_Xhi;
    const bf16* Bp = (pass == 2) ? d_Gtlo : d_Gthi;
    int Khalf = KXC >> 1;
    float* outp = d_part + (size_t)z * (RR*HH);
    gemm_mma_body(Ap, Bp, KXC, ks*Khalf, Khalf, HH,
                  blockIdx.x, blockIdx.y, outp, &sm);
}

// ===== K5: mlp_tail: h1 = relu(sum 6 partials + E1[tok]), out = h1@W2t + b2 =====
__global__ void __launch_bounds__(256) mlp_tail(const int* __restrict__ tokens,
                                                const float* __restrict__ b2,
                                                float* __restrict__ out) {
    __shared__ __align__(16) float hs[4][HH];
    int tid = threadIdx.x;
    int r0 = blockIdx.x * 4;
    int e = tid * 8, row = e >> 9, col = e & 511;
    int rr = r0 + row;
    int tok = tokens[(rr >> 4)*LL + (LL - TOUT) + (rr & 15)];
    int gi = rr*HH + col;
    const float* e1 = d_E1 + (size_t)tok*HH + col;
    float4 s0 = *(const float4*)(e1);
    float4 s1 = *(const float4*)(e1 + 4);
    #pragma unroll
    for (int z = 0; z < NZF; ++z) {
        const float* pp = d_part + (size_t)z*RR*HH + gi;
        float4 p0 = *(const float4*)pp;
        float4 p1 = *(const float4*)(pp + 4);
        s0.x += p0.x; s0.y += p0.y; s0.z += p0.z; s0.w += p0.w;
        s1.x += p1.x; s1.y += p1.y; s1.z += p1.z; s1.w += p1.w;
    }
    s0.x = fmaxf(s0.x, 0.f); s0.y = fmaxf(s0.y, 0.f);
    s0.z = fmaxf(s0.z, 0.f); s0.w = fmaxf(s0.w, 0.f);
    s1.x = fmaxf(s1.x, 0.f); s1.y = fmaxf(s1.y, 0.f);
    s1.z = fmaxf(s1.z, 0.f); s1.w = fmaxf(s1.w, 0.f);
    *(float4*)&hs[row][col]     = s0;
    *(float4*)&hs[row][col + 4] = s1;
    __syncthreads();
    if (tid < 128) {
        int rw = tid >> 5, v = tid & 31;
        const float* wr = d_W2t + (size_t)v*HH;
        u64 a = 0ull, b = 0ull;
        #pragma unroll 8
        for (int h = 0; h < HH; h += 4) {
            ulonglong2 hv = *(const ulonglong2*)&hs[rw][h];
            ulonglong2 wv = *(const ulonglong2*)(wr + h);
            a = fma2(hv.x, wv.x, a);
            b = fma2(hv.y, wv.y, b);
        }
        float2 fa = upk(a), fb = upk(b);
        out[(r0 + rw)*VV + v] = fa.x + fa.y + fb.x + fb.y + b2[v];
    }
}

// ================= launcher =================
extern "C" void kernel_launch(void* const* d_in, const int* in_sizes, int n_in,
                              void* d_out, int out_size) {
    const int*   tokens  = (const int*)  d_in[0];
    const float* embed   = (const float*)d_in[1];
    const float* Lre     = (const float*)d_in[2];
    const float* Lim     = (const float*)d_in[3];
    const float* Bre     = (const float*)d_in[4];
    const float* Bim     = (const float*)d_in[5];
    const float* Cre     = (const float*)d_in[6];
    const float* Cim     = (const float*)d_in[7];
    const float* D       = (const float*)d_in[8];
    const float* logstep = (const float*)d_in[9];
    const float* W1      = (const float*)d_in[10];
    const float* b1      = (const float*)d_in[11];
    const float* W2      = (const float*)d_in[12];
    const float* b2      = (const float*)d_in[13];
    float* out = (float*)d_out;

    prep_all<<<1068, 256>>>(Lre, Lim, logstep, embed, Bre, Bim, W2, Cre, Cim, D, W1);
    scan_gemmGt<<<NC*BSZ + NZG*112, 128>>>(tokens);
    combine_reduceG<<<512, 256>>>(tokens, b1);
    gemmF<<<dim3(8, 8, NZF), 128>>>();
    mlp_tail<<<RR/4, 256>>>(tokens, b2, out);
}